// round 10
// baseline (speedup 1.0000x reference)
#include <cuda_runtime.h>
#include <cstddef>
#include <cstdint>

// Problem constants: B=2, S=512, H=256, A=128
#define BB 2
#define SS 512
#define HH 256
#define AA 128
#define HCH 8          // h-columns per scan block
#define XPAD 516       // smem row pitch for scan transpose

// Scratch (device globals; no allocs allowed)
__device__ float g_part[2 * BB * SS];   // per-a-half row partials (pre-sum)
__device__ float g_w[BB * SS];          // e_j * am_j
__device__ float g_scale[BB * SS];      // am_i / C_i

// ---------------------------------------------------------------------------
// Kernel 1: partial scores. Block = (row-oct, a-half): 8 rows x 64 a-cols,
// full K=256. grid 256 -> 2 co-resident blocks/SM -> 8 warps/SMSP (hide
// latency by warp count, not ring depth).
// Warp = (hr = wid>>1: 32 h, ch = wid&1: 32 of the 64 cols).
// Per-warp cp.async 4-slot ring, distance 3. Static smem 40KB.
// ---------------------------------------------------------------------------
__global__ __launch_bounds__(512) void k_score(
    const float* __restrict__ x, const float* __restrict__ w_a,
    const float* __restrict__ query)
{
    __shared__ float pool[10240];        // 40KB: xsT(2048) + staging(16*512)
    __shared__ float part[8][2];
    float* xsT = pool;                                   // [h*8 + r]
    float* stg = pool + 2048;                            // wid*512 + slot*128
    unsigned long long* sredU =
        reinterpret_cast<unsigned long long*>(pool + 2048);  // [hr*4+rp][64]

    const int tid  = threadIdx.x;
    const int lane = tid & 31;
    const int wid  = tid >> 5;
    const int hr   = wid >> 1;            // h-range 0..7 (32 h each)
    const int ch   = wid & 1;             // col sub-half 0/1 (32 cols)
    const int h0   = hr * 32;
    const int ah   = blockIdx.x & 1;      // a-half 0/1 (64 cols)
    const int r0   = (blockIdx.x >> 1) * 8;

    // per-lane cp.async: chunk = 4h x 32col = 512B; lane owns 16B
    // write offset lane*4 floats == (lane>>3)*32 + (lane&7)*4  (hl-major)
    const float* wsrc = w_a + (size_t)(h0 + (lane >> 3)) * AA
                            + ah * 64 + ch * 32 + (lane & 7) * 4;
    const uint32_t wdst =
        (uint32_t)__cvta_generic_to_shared(stg + wid * 512 + lane * 4);

#define ISSUE(c)                                                             \
    asm volatile(                                                            \
        "cp.async.cg.shared.global [%0], [%1], 16;\n\t"                      \
        "cp.async.commit_group;"                                             \
        :: "r"(wdst + (uint32_t)(((c) & 3) * 512)),                          \
           "l"(wsrc + (size_t)(c) * 4 * AA) : "memory")

    ISSUE(0); ISSUE(1); ISSUE(2); ISSUE(3);

    // stage 8 rows of x transposed: xsT[h*8 + r] (overlaps with prefetches)
    {
        const int r  = tid & 7;
        const int h4 = tid >> 3;           // 0..63
        const float4 v =
            reinterpret_cast<const float4*>(x + (size_t)r0 * HH)[r * 64 + h4];
        xsT[(h4 * 4 + 0) * 8 + r] = v.x;
        xsT[(h4 * 4 + 1) * 8 + r] = v.y;
        xsT[(h4 * 4 + 2) * 8 + r] = v.z;
        xsT[(h4 * 4 + 3) * 8 + r] = v.w;
    }
    __syncthreads();                       // xsT ready (barrier #1)

    // 4 f32x2 accumulators = 8 rows, 1 col per lane
    unsigned long long acc0=0, acc1=0, acc2=0, acc3=0;

#define COMPUTE(c)                                                           \
    do {                                                                     \
        const float* wb = stg + wid * 512 + ((c) & 3) * 128;                 \
        _Pragma("unroll")                                                    \
        for (int hl = 0; hl < 4; ++hl) {                                     \
            const float wv = wb[hl * 32 + lane];                             \
            unsigned long long wd;                                           \
            asm("mov.b64 %0, {%1, %1};" : "=l"(wd) : "f"(wv));               \
            const unsigned long long* xr =                                   \
                reinterpret_cast<const unsigned long long*>(                 \
                    xsT + (h0 + (c) * 4 + hl) * 8);                          \
            asm("fma.rn.f32x2 %0, %1, %2, %0;" : "+l"(acc0) : "l"(xr[0]), "l"(wd)); \
            asm("fma.rn.f32x2 %0, %1, %2, %0;" : "+l"(acc1) : "l"(xr[1]), "l"(wd)); \
            asm("fma.rn.f32x2 %0, %1, %2, %0;" : "+l"(acc2) : "l"(xr[2]), "l"(wd)); \
            asm("fma.rn.f32x2 %0, %1, %2, %0;" : "+l"(acc3) : "l"(xr[3]), "l"(wd)); \
        }                                                                    \
    } while (0)

#define WAITW(n) asm volatile("cp.async.wait_group " #n ";" ::: "memory"); __syncwarp()

    WAITW(3); COMPUTE(0); ISSUE(4);
    WAITW(3); COMPUTE(1); ISSUE(5);
    WAITW(3); COMPUTE(2); ISSUE(6);
    WAITW(3); COMPUTE(3); ISSUE(7);
    WAITW(3); COMPUTE(4);
    WAITW(2); COMPUTE(5);
    WAITW(1); COMPUTE(6);
    WAITW(0); COMPUTE(7);
#undef ISSUE
#undef COMPUTE
#undef WAITW

    __syncthreads();                       // staging free (barrier #2)

    // partials: sredU[(hr*4+rp)*64 + ch*32+lane]
    {
        const int c0 = ch * 32 + lane;
        unsigned long long av[4] = {acc0, acc1, acc2, acc3};
#pragma unroll
        for (int rp = 0; rp < 4; ++rp)
            sredU[(hr * 4 + rp) * 64 + c0] = av[rp];
    }
    __syncthreads();                       // sred ready (barrier #3)

    // epilogue (threads 0..255): rp = tid>>6, col = tid&63
    if (tid < 256) {
        const int rp  = tid >> 6;
        const int col = tid & 63;
        float v0 = 0.f, v1 = 0.f;
#pragma unroll
        for (int hg = 0; hg < 8; ++hg) {
            float lo, hi;
            asm("mov.b64 {%0, %1}, %2;" : "=f"(lo), "=f"(hi)
                : "l"(sredU[(hg * 4 + rp) * 64 + col]));
            v0 += lo; v1 += hi;
        }
        const float qv = query[ah * 64 + col];
        float slo = qv * tanhf(v0);        // row 2*rp
        float shi = qv * tanhf(v1);        // row 2*rp+1
#pragma unroll
        for (int o = 16; o > 0; o >>= 1) {
            slo += __shfl_down_sync(0xffffffffu, slo, o);
            shi += __shfl_down_sync(0xffffffffu, shi, o);
        }
        if (lane == 0) { part[tid >> 5][0] = slo; part[tid >> 5][1] = shi; }
    }
    __syncthreads();
    if (tid < 8) {
        const int rp  = tid >> 1;          // row-pair
        const int sel = tid & 1;
        g_part[ah * (BB * SS) + r0 + tid] =
            part[rp * 2][sel] + part[rp * 2 + 1][sel];
    }
}

// ---------------------------------------------------------------------------
// Kernel 2: combine a-halves, then per-batch max + exp + prefix sum.
// ---------------------------------------------------------------------------
__global__ __launch_bounds__(512) void k_scan(const int* __restrict__ amask)
{
    const int b = blockIdx.x, tid = threadIdx.x;
    const int lane = tid & 31, wid = tid >> 5;   // 16 warps
    __shared__ float wmax[16], wsum[16];

    const float sv = g_part[b * SS + tid] + g_part[BB * SS + b * SS + tid];

    float m = sv;
#pragma unroll
    for (int o = 16; o > 0; o >>= 1) m = fmaxf(m, __shfl_xor_sync(0xffffffffu, m, o));
    if (lane == 0) wmax[wid] = m;
    __syncthreads();
    float M = wmax[0];
#pragma unroll
    for (int k = 1; k < 16; ++k) M = fmaxf(M, wmax[k]);

    const float e = expf(sv - M);

    float sc = e;
#pragma unroll
    for (int o = 1; o < 32; o <<= 1) {
        const float t = __shfl_up_sync(0xffffffffu, sc, o);
        if (lane >= o) sc += t;
    }
    if (lane == 31) wsum[wid] = sc;
    __syncthreads();
    float off = 0.f;
#pragma unroll
    for (int k = 0; k < 16; ++k)
        if (k < wid) off += wsum[k];

    const float C  = sc + off;
    const int   am = amask[b * SS + tid];
    g_w[b * SS + tid]     = am ? e : 0.f;
    g_scale[b * SS + tid] = am ? (1.f / C) : 0.f;
}

// ---------------------------------------------------------------------------
// Kernel 3 (fused): grid (256 + 32, B), 512 threads.
//  bx < 256 : write 2 rows of d (float2 stores).
//  bx >= 256: column-scan block computing a[b, :, h0..h0+7] directly.
// ---------------------------------------------------------------------------
__global__ __launch_bounds__(512) void k_fused(
    const float* __restrict__ x, float* __restrict__ d_out,
    float* __restrict__ a_out)
{
    const int b = blockIdx.y, tid = threadIdx.x;

    if (blockIdx.x < 256) {
        const int rp = tid >> 8;             // 0/1
        const int sl = tid & 255;            // float2 slot
        const int i  = blockIdx.x * 2 + rp;
        const float sc = g_scale[b * SS + i];
        const float2 w2 = reinterpret_cast<const float2*>(g_w + b * SS)[sl];
        const int j0 = sl * 2;
        float2 o;
        o.x = (j0     <= i) ? w2.x * sc : 0.f;
        o.y = (j0 + 1 <= i) ? w2.y * sc : 0.f;
        reinterpret_cast<float2*>(d_out + (size_t)(b * SS + i) * SS)[sl] = o;
        return;
    }

    // ---- a-scan part ----
    __shared__ float xt[HCH][XPAD];
    __shared__ float ws[SS], scs[SS];
    __shared__ float htot[HCH];

    const int h0 = (blockIdx.x - 256) * HCH;

    ws[tid]  = g_w[b * SS + tid];
    scs[tid] = g_scale[b * SS + tid];

    const float* xb = x + (size_t)b * SS * HH + h0;
#pragma unroll
    for (int it = 0; it < HCH; ++it) {
        const int flat = it * 512 + tid;     // 0..4095
        const int j  = flat >> 3;
        const int hh = flat & 7;
        xt[hh][j] = xb[(size_t)j * HH + hh];
    }
    __syncthreads();

    const int lane = tid & 31, wid = tid >> 5;
    const int hh   = wid >> 1;               // h-column 0..7
    const int half = wid & 1;                // j-half 0/1
    const int jb   = half * 256;

    float carry = 0.f;
    float vals[8];
#pragma unroll
    for (int k = 0; k < 8; ++k) {
        const int j = jb + k * 32 + lane;
        float v = xt[hh][j] * ws[j];
#pragma unroll
        for (int o = 1; o < 32; o <<= 1) {
            const float t = __shfl_up_sync(0xffffffffu, v, o);
            if (lane >= o) v += t;
        }
        v += carry;
        carry = __shfl_sync(0xffffffffu, v, 31);
        vals[k] = v;
    }
    if (half == 0 && lane == 31) htot[hh] = carry;
    __syncthreads();

    const float base = half ? htot[hh] : 0.f;
#pragma unroll
    for (int k = 0; k < 8; ++k) {
        const int j = jb + k * 32 + lane;
        xt[hh][j] = (vals[k] + base) * scs[j];
    }
    __syncthreads();

    float* ab = a_out + (size_t)b * SS * HH + h0;
#pragma unroll
    for (int it = 0; it < HCH; ++it) {
        const int flat = it * 512 + tid;
        const int j  = flat >> 3;
        const int h2 = flat & 7;
        ab[(size_t)j * HH + h2] = xt[h2][j];
    }
}

// ---------------------------------------------------------------------------
extern "C" void kernel_launch(void* const* d_in, const int* in_sizes, int n_in,
                              void* d_out, int out_size)
{
    const float* x     = (const float*)d_in[0];   // (B,S,H)
    const int*   amask = (const int*)  d_in[1];   // (B,S)
    const float* w_a   = (const float*)d_in[2];   // (H,A)
    const float* query = (const float*)d_in[3];   // (A,)

    float* out   = (float*)d_out;
    float* a_out = out;                                // (B,S,H) first
    float* dd    = out + (size_t)BB * SS * HH;         // (B,S,S) second

    k_score<<<(BB * SS) / 8 * 2, 512>>>(x, w_a, query);
    k_scan<<<BB, SS>>>(amask);
    k_fused<<<dim3(256 + HH / HCH, BB), 512>>>(x, dd, a_out);
}